// round 1
// baseline (speedup 1.0000x reference)
#include <cuda_runtime.h>
#include <math.h>

// Problem constants
#define B_   32
#define C_   256
#define L_   8192
#define H_   16
#define ROWS (B_ * C_)            // 8192 (b,c) rows
#define L4   (L_ / 4)             // 2048 float4 per row
#define TOT4 ((size_t)ROWS * L4)  // 16,777,216 float4 total

// Scratch (allocation-free rule: __device__ globals)
__device__ float d_y[ROWS];   // per-(b,c) means
__device__ float d_g[ROWS];   // per-(b,c) gates

// ---------------------------------------------------------------------------
// K1: mean over L per row. One block per row, 256 threads, float4 loads.
// ---------------------------------------------------------------------------
__global__ __launch_bounds__(256) void se_mean_kernel(const float4* __restrict__ x) {
    const int row = blockIdx.x;
    const float4* __restrict__ p = x + (size_t)row * L4;

    float s = 0.0f;
    #pragma unroll 8
    for (int i = threadIdx.x; i < L4; i += 256) {
        float4 v = __ldg(p + i);
        s += (v.x + v.y) + (v.z + v.w);
    }

    // warp reduce
    #pragma unroll
    for (int off = 16; off > 0; off >>= 1)
        s += __shfl_xor_sync(0xFFFFFFFFu, s, off);

    __shared__ float warp_sums[8];
    const int lane = threadIdx.x & 31;
    const int wid  = threadIdx.x >> 5;
    if (lane == 0) warp_sums[wid] = s;
    __syncthreads();

    if (wid == 0) {
        float t = (lane < 8) ? warp_sums[lane] : 0.0f;
        #pragma unroll
        for (int off = 4; off > 0; off >>= 1)
            t += __shfl_xor_sync(0xFFFFFFFFu, t, off);
        if (lane == 0) d_y[row] = t * (1.0f / (float)L_);
    }
}

// ---------------------------------------------------------------------------
// K2: excite MLP. One block per batch. W1: [H, C] row-major, W2: [C, H].
// h[j] = relu(sum_c y[c] * W1[j*C + c]);  g[c] = sigmoid(sum_j h[j] * W2[c*H + j])
// ---------------------------------------------------------------------------
__global__ __launch_bounds__(256) void se_excite_kernel(const float* __restrict__ W1,
                                                        const float* __restrict__ W2) {
    const int b = blockIdx.x;
    const int t = threadIdx.x;
    __shared__ float ys[C_];
    __shared__ float hs[H_];

    ys[t] = d_y[b * C_ + t];
    __syncthreads();

    if (t < H_) {
        float s = 0.0f;
        const float* __restrict__ w = W1 + t * C_;
        #pragma unroll 8
        for (int c = 0; c < C_; ++c) s += ys[c] * w[c];
        hs[t] = fmaxf(s, 0.0f);
    }
    __syncthreads();

    float s = 0.0f;
    const float* __restrict__ w2 = W2 + t * H_;
    #pragma unroll
    for (int j = 0; j < H_; ++j) s += hs[j] * w2[j];
    d_g[b * C_ + t] = 1.0f / (1.0f + expf(-s));
}

// ---------------------------------------------------------------------------
// K3: out = x * g[row]. One float4 per thread; row = idx >> 11 (warp-uniform).
// ---------------------------------------------------------------------------
__global__ __launch_bounds__(256) void se_scale_kernel(const float4* __restrict__ x,
                                                       float4* __restrict__ out) {
    const size_t i = (size_t)blockIdx.x * 256 + threadIdx.x;
    const int row = (int)(i >> 11);      // L4 = 2048 = 1<<11
    const float gv = d_g[row];
    float4 v = __ldg(x + i);
    v.x *= gv; v.y *= gv; v.z *= gv; v.w *= gv;
    out[i] = v;
}

// ---------------------------------------------------------------------------
extern "C" void kernel_launch(void* const* d_in, const int* in_sizes, int n_in,
                              void* d_out, int out_size) {
    const float4* x  = (const float4*)d_in[0];
    const float*  W1 = (const float*)d_in[1];
    const float*  W2 = (const float*)d_in[2];
    float4* out = (float4*)d_out;

    se_mean_kernel<<<ROWS, 256>>>(x);
    se_excite_kernel<<<B_, 256>>>(W1, W2);
    se_scale_kernel<<<(unsigned)(TOT4 / 256), 256>>>(x, out);
}